// round 4
// baseline (speedup 1.0000x reference)
#include <cuda_runtime.h>
#include <cuda_bf16.h>
#include <math.h>

#define KBINS 5
#define TAILB 2.5f
#define TPB 256

// Per-bin table, 2 float4 used + 1 float4 pad (48B stride -> conflict-free LDS):
//   g_tab[3b+0] = A = {p2, p1, p0, q2}   den(x)  = p2 x^2 + p1 x + p0
//   g_tab[3b+1] = B = {q1, q0, r1, r0}   numz(x) = q2 x^2 + q1 x + q0 (y_k folded)
//                                        num2(x) = -p2 x^2 + r1 x + r0 (identity)
// All scaled by 1/s^2 so that lj = log(num2/den^2) exactly (2*log s folded).
__device__ float4 g_tab[3 * KBINS];
__device__ float  g_bnd[4];   // interior bin boundaries cum_w[1..4]

__global__ void rqs_setup_kernel(const float* __restrict__ params) {
    if (threadIdx.x != 0) return;

    float W[KBINS], H[KBINS], D[KBINS + 1];

    { // softmax(widths) * 2*TAILB
        float mx = params[0];
        #pragma unroll
        for (int i = 1; i < KBINS; i++) mx = fmaxf(mx, params[i]);
        float s = 0.f, e[KBINS];
        #pragma unroll
        for (int i = 0; i < KBINS; i++) { e[i] = expf(params[i] - mx); s += e[i]; }
        #pragma unroll
        for (int i = 0; i < KBINS; i++) W[i] = e[i] / s * (2.0f * TAILB);
    }
    { // softmax(heights) * 2*TAILB
        float mx = params[KBINS];
        #pragma unroll
        for (int i = 1; i < KBINS; i++) mx = fmaxf(mx, params[KBINS + i]);
        float s = 0.f, e[KBINS];
        #pragma unroll
        for (int i = 0; i < KBINS; i++) { e[i] = expf(params[KBINS + i] - mx); s += e[i]; }
        #pragma unroll
        for (int i = 0; i < KBINS; i++) H[i] = e[i] / s * (2.0f * TAILB);
    }
    #pragma unroll
    for (int i = 0; i < KBINS + 1; i++) { // softplus + 1e-5
        float v = params[2 * KBINS + i];
        D[i] = log1pf(expf(-fabsf(v))) + fmaxf(v, 0.0f) + 1e-5f;
    }

    float cw[KBINS + 1], ch[KBINS + 1];
    cw[0] = -TAILB; ch[0] = -TAILB;
    float aw = 0.f, ah = 0.f;
    #pragma unroll
    for (int i = 0; i < KBINS; i++) {
        aw += W[i]; cw[i + 1] = aw - TAILB;
        ah += H[i]; ch[i + 1] = ah - TAILB;
    }

    #pragma unroll
    for (int bi = 0; bi < KBINS; bi++) {
        float xk  = cw[bi];
        float yk  = ch[bi];
        float dy  = ch[bi + 1] - ch[bi];
        float dk  = D[bi], dk1 = D[bi + 1];
        float s   = H[bi] / W[bi];
        float c   = dk + dk1 - 2.0f * s;
        float sd  = s - dk;
        // xi = a*x + b_
        float a  = 1.0f / (cw[bi + 1] - cw[bi] + 1e-8f);
        float b_ = -a * xk;

        // den = -c v^2 + c v + s
        float p2 = -c * a * a;
        float p1 = c * a * (1.0f - 2.0f * b_);
        float p0 = s + c * (b_ - b_ * b_);
        // numz = dy*(sd v^2 + dk v), then fold y_k: q^ = q + yk*p
        float q2 = dy * sd * a * a + yk * p2;
        float q1 = dy * a * (2.0f * b_ * sd + dk) + yk * p1;
        float q0 = dy * (sd * b_ * b_ + dk * b_) + yk * p0;
        // num2 = c v^2 + 2 sd v + dk   (leading coeff = -p2 -> derived at runtime)
        float r1 = 2.0f * a * (c * b_ + sd);
        float r0 = c * b_ * b_ + 2.0f * sd * b_ + dk;

        float is2 = 1.0f / (s * s);
        g_tab[3 * bi + 0] = make_float4(p2 * is2, p1 * is2, p0 * is2, q2 * is2);
        g_tab[3 * bi + 1] = make_float4(q1 * is2, q0 * is2, r1 * is2, r0 * is2);
        g_tab[3 * bi + 2] = make_float4(0.f, 0.f, 0.f, 0.f);  // pad (bank spread)
    }
    #pragma unroll
    for (int i = 0; i < 4; i++) g_bnd[i] = cw[i + 1];
}

// Single-instruction MUFU paths (pipe is otherwise idle; saves issue slots)
__device__ __forceinline__ float rcp_approx(float x) {
    float r; asm("rcp.approx.f32 %0, %1;" : "=f"(r) : "f"(x)); return r;
}
__device__ __forceinline__ float lg2_approx(float x) {
    float r; asm("lg2.approx.f32 %0, %1;" : "=f"(r) : "f"(x)); return r;
}

__device__ __forceinline__ void rqs_one(
    float x, float b0, float b1, float b2, float b3,
    const float4* __restrict__ sh, float& zo, float& lo)
{
    bool inside = fabsf(x) <= TAILB;
    float xs = inside ? x : 0.0f;
    int off = ((xs > b0) + (xs > b1) + (xs > b2) + (xs > b3)) * 3;

    float4 A = sh[off];
    float4 B = sh[off + 1];

    float den  = fmaf(fmaf(A.x, xs, A.y), xs, A.z);
    float numz = fmaf(fmaf(A.w, xs, B.x), xs, B.y);
    float num2 = fmaf(fmaf(-A.x, xs, B.z), xs, B.w);

    float rA = rcp_approx(den);
    float z  = numz * rA;                    // y_k folded in

    float larg = (num2 * rA) * rA;           // s^2 scaling folded in table
    float lj   = 0.69314718056f * lg2_approx(larg);

    zo = inside ? z : x;
    lo = inside ? lj : 0.0f;
}

__global__ void __launch_bounds__(TPB)
rqs_main_kernel(const float* __restrict__ x, float* __restrict__ out, int n4)
{
    __shared__ float4 sh[3 * KBINS];
    int tid = threadIdx.x;
    if (tid < 3 * KBINS) sh[tid] = g_tab[tid];
    __syncthreads();

    float b0 = g_bnd[0], b1 = g_bnd[1], b2 = g_bnd[2], b3 = g_bnd[3];

    const float4* __restrict__ x4 = (const float4*)x;
    float4* __restrict__ z4 = (float4*)out;
    float4* __restrict__ l4 = (float4*)(out + ((size_t)n4 * 4));

    int base = blockIdx.x * (TPB * 2) + tid;

    #pragma unroll
    for (int k = 0; k < 2; k++) {
        int i = base + k * TPB;
        if (i < n4) {
            float4 xv = x4[i];
            float4 zv, lv;
            rqs_one(xv.x, b0, b1, b2, b3, sh, zv.x, lv.x);
            rqs_one(xv.y, b0, b1, b2, b3, sh, zv.y, lv.y);
            rqs_one(xv.z, b0, b1, b2, b3, sh, zv.z, lv.z);
            rqs_one(xv.w, b0, b1, b2, b3, sh, zv.w, lv.w);
            z4[i] = zv;
            l4[i] = lv;
        }
    }
}

extern "C" void kernel_launch(void* const* d_in, const int* in_sizes, int n_in,
                              void* d_out, int out_size)
{
    const float* x      = (const float*)d_in[0];
    const float* params = (const float*)d_in[1];
    float* out          = (float*)d_out;

    int n  = in_sizes[0];     // 16777216
    int n4 = n >> 2;          // float4 count

    rqs_setup_kernel<<<1, 32>>>(params);

    int blocks = (n4 + TPB * 2 - 1) / (TPB * 2);
    rqs_main_kernel<<<blocks, TPB>>>(x, out, n4);
}